// round 6
// baseline (speedup 1.0000x reference)
#include <cuda_runtime.h>

#define N_VOX        1024
#define NUM_RAYS     2048
#define N_SH         9
#define NS           8
#define THREADS      128           // 4 warps cooperating on ONE ray
#define WARPS        4
#define VOX_PER_WARP (N_VOX / WARPS)   // 256 -> 8 tests per lane
#define CAP          128
#define CHUNKS       (CAP / 32)
#define EARLY_STOP_T 0.01f
#define FAR_PLANE    100.0f
#define FULL         0xffffffffu

// float -> order-preserving uint32 (ascending float == ascending uint)
__device__ __forceinline__ unsigned f2u(float f) {
    unsigned u = __float_as_uint(f);
    return (u & 0x80000000u) ? ~u : (u | 0x80000000u);
}

__device__ __forceinline__ float fast_sigmoid(float a) {
    return __fdividef(1.0f, 1.0f + __expf(-a));
}

__global__ void __launch_bounds__(THREADS)
voxel_raster_kernel(const float* __restrict__ positions,   // [N,3]
                    const float* __restrict__ sizes,       // [N]
                    const float* __restrict__ densities,   // [N]
                    const float* __restrict__ colors,      // [N, 27]
                    const float* __restrict__ ray_o,       // [B,3]
                    const float* __restrict__ ray_d,       // [B,3]
                    float* __restrict__ out)               // rgb[3B] | depth[B] | weight[B]
{
    __shared__ unsigned long long s_keys[CAP];
    __shared__ float s_tf_src[CAP];
    __shared__ float s_tf_dst[CAP];
    __shared__ int   s_cnt;

    const int b    = blockIdx.x;
    const int warp = threadIdx.x >> 5;
    const int lane = threadIdx.x & 31;

    if (threadIdx.x == 0) s_cnt = 0;
    __syncthreads();

    const float ox = ray_o[b * 3 + 0];
    const float oy = ray_o[b * 3 + 1];
    const float oz = ray_o[b * 3 + 2];
    const float dx = ray_d[b * 3 + 0];
    const float dy = ray_d[b * 3 + 1];
    const float dz = ray_d[b * 3 + 2];
    const float ix = __fdividef(1.0f, dx);
    const float iy = __fdividef(1.0f, dy);
    const float iz = __fdividef(1.0f, dz);
    const float nx = -ox * ix, ny = -oy * iy, nz = -oz * iz;
    const float axr = fabsf(ix), ayr = fabsf(iy), azr = fabsf(iz);

    // ---------------- Phase 1: slab tests, per-lane atomic push ----------------
    #pragma unroll
    for (int i = 0; i < VOX_PER_WARP / 32; i++) {
        const int v = warp * VOX_PER_WARP + i * 32 + lane;

        const float px = positions[v * 3 + 0];
        const float py = positions[v * 3 + 1];
        const float pz = positions[v * 3 + 2];
        const float h  = 0.5f * sizes[v];

        // slab via center/extent: tc +- h*|inv|
        const float tcx = fmaf(px, ix, nx);
        const float tcy = fmaf(py, iy, ny);
        const float tcz = fmaf(pz, iz, nz);
        const float hx = h * axr, hy = h * ayr, hz = h * azr;

        const float tn = fmaxf(fmaxf(tcx - hx, tcy - hy), tcz - hz);
        const float tf = fminf(fminf(tcx + hx, tcy + hy), tcz + hz);

        if (tf > fmaxf(tn, 0.0f)) {
            const int slot = atomicAdd(&s_cnt, 1);
            if (slot < CAP) {
                s_keys[slot]   = ((unsigned long long)f2u(tn) << 32) | (unsigned)v;
                s_tf_src[slot] = tf;
            }
        }
    }
    __syncthreads();

    // ---------------- Phases 2+3: warp 0 only ----------------
    if (warp != 0) return;

    const int n = min(s_cnt, CAP);

    // ---- rank sort by (tn, voxel idx); keys are unique 64-bit ----
    if (n > 1) {
        unsigned long long myk[CHUNKS];
        float mytf[CHUNKS];
        int   myr[CHUNKS];
        #pragma unroll
        for (int c = 0; c < CHUNKS; c++) {
            const int e = c * 32 + lane;
            myr[c] = -1;
            if (e < n) {
                const unsigned long long k = s_keys[e];
                int r = 0;
                for (int j = 0; j < n; j++) r += (s_keys[j] < k);
                myk[c]  = k;
                mytf[c] = s_tf_src[e];
                myr[c]  = r;
            }
        }
        __syncwarp();
        #pragma unroll
        for (int c = 0; c < CHUNKS; c++)
            if (myr[c] >= 0) { s_keys[myr[c]] = myk[c]; s_tf_dst[myr[c]] = mytf[c]; }
        __syncwarp();
    } else if (n == 1) {
        if (lane == 0) s_tf_dst[0] = s_tf_src[0];
        __syncwarp();
    }

    // SH degree-2 basis, reference order: [1, y, z, x, xy, yz, 3z^2-1, xz, x^2-y^2]
    float sh[N_SH];
    sh[0] = 1.0f;
    sh[1] = dy;  sh[2] = dz;  sh[3] = dx;
    sh[4] = dx * dy;  sh[5] = dy * dz;
    sh[6] = 3.0f * dz * dz - 1.0f;
    sh[7] = dx * dz;  sh[8] = dx * dx - dy * dy;

    // ---- warp-parallel composite: prefix-product scan per 32-chunk ----
    float T_carry = 1.0f;
    float rA = 0.0f, gA = 0.0f, bA = 0.0f, dA = 0.0f, wA = 0.0f;

    for (int base = 0; base < n; base += 32) {
        const int e = base + lane;
        float ws = 0.0f, dp = 0.0f, cr = 0.0f, cg = 0.0f, cb = 0.0f;

        if (e < n) {
            const unsigned long long key = s_keys[e];
            const unsigned v  = (unsigned)(key & 0xFFFFFFFFu);

            // front-batch the gathered loads so they overlap the arithmetic below
            const float dens = densities[v];
            const float* c = colors + v * (3 * N_SH);
            float cv[3 * N_SH];
            #pragma unroll
            for (int k = 0; k < 3 * N_SH; k++) cv[k] = c[k];

            unsigned tu = (unsigned)(key >> 32);
            const float tn = __uint_as_float((tu & 0x80000000u) ? (tu & 0x7FFFFFFFu) : ~tu);
            const float tf = s_tf_dst[e];

            const float sigma = __expf(dens);
            const float span  = tf - tn;
            const float delta = span * (1.0f / (float)NS);
            const float alpha = 1.0f - __expf(-sigma * delta);
            const float bse   = 1.0f - alpha + 1e-8f;

            float pw = 1.0f;
            #pragma unroll
            for (int s = 0; s < NS; s++) {
                const float w  = alpha * pw;
                const float ts = tn + span * ((float)s / (float)(NS - 1));
                ws += w;
                dp += w * ts;
                pw *= bse;
            }

            float a0 = 0.0f, a1 = 0.0f, a2 = 0.0f;
            #pragma unroll
            for (int k = 0; k < N_SH; k++) {
                a0 += sh[k] * cv[k];
                a1 += sh[k] * cv[N_SH + k];
                a2 += sh[k] * cv[2 * N_SH + k];
            }
            cr = fast_sigmoid(a0);
            cg = fast_sigmoid(a1);
            cb = fast_sigmoid(a2);
        }

        // inclusive prefix product of one_m (inactive lanes contribute 1.0)
        float pp = 1.0f - ws;
        #pragma unroll
        for (int off = 1; off < 32; off <<= 1) {
            const float vv = __shfl_up_sync(FULL, pp, off);
            if (lane >= off) pp *= vv;
        }
        float ex = __shfl_up_sync(FULL, pp, 1);
        if (lane == 0) ex = 1.0f;
        const float Tb = T_carry * ex;

        const float procf   = (Tb >= EARLY_STOP_T) ? 1.0f : 0.0f;
        const float contrib = Tb * ws * procf;
        rA += contrib * cr;
        gA += contrib * cg;
        bA += contrib * cb;
        dA += Tb * procf * dp;
        wA += contrib;

        T_carry *= __shfl_sync(FULL, pp, 31);
        if (T_carry < EARLY_STOP_T && base + 32 < n) break;  // all later proc = 0
    }

    // warp reductions
    #pragma unroll
    for (int off = 16; off > 0; off >>= 1) {
        rA += __shfl_down_sync(FULL, rA, off);
        gA += __shfl_down_sync(FULL, gA, off);
        bA += __shfl_down_sync(FULL, bA, off);
        dA += __shfl_down_sync(FULL, dA, off);
        wA += __shfl_down_sync(FULL, wA, off);
    }

    if (lane == 0) {
        out[b * 3 + 0] = rA;
        out[b * 3 + 1] = gA;
        out[b * 3 + 2] = bA;
        out[NUM_RAYS * 3 + b] = (n > 0) ? dA : FAR_PLANE;   // has_hit == (n > 0)
        out[NUM_RAYS * 4 + b] = wA;
    }
}

extern "C" void kernel_launch(void* const* d_in, const int* in_sizes, int n_in,
                              void* d_out, int out_size) {
    const float* positions = (const float*)d_in[0];
    const float* sizes     = (const float*)d_in[1];
    const float* densities = (const float*)d_in[2];
    const float* colors    = (const float*)d_in[3];
    const float* ray_o     = (const float*)d_in[4];
    const float* ray_d     = (const float*)d_in[5];
    float* out = (float*)d_out;

    voxel_raster_kernel<<<NUM_RAYS, THREADS>>>(positions, sizes, densities, colors,
                                               ray_o, ray_d, out);
}

// round 7
// speedup vs baseline: 1.0029x; 1.0029x over previous
#include <cuda_runtime.h>

#define N_VOX        1024
#define NUM_RAYS     2048
#define N_SH         9
#define NS           8
#define THREADS      128           // 4 warps cooperating on ONE ray
#define WARPS        4
#define PAIRS_PER_WARP (N_VOX / 2 / WARPS)   // 128 pairs -> 4 pair-iters per lane
#define CAP          128
#define CHUNKS       (CAP / 32)
#define EARLY_STOP_T 0.01f
#define FAR_PLANE    100.0f
#define FULL         0xffffffffu

// float -> order-preserving uint32 (ascending float == ascending uint)
__device__ __forceinline__ unsigned f2u(float f) {
    unsigned u = __float_as_uint(f);
    return (u & 0x80000000u) ? ~u : (u | 0x80000000u);
}

__device__ __forceinline__ float fast_sigmoid(float a) {
    return __fdividef(1.0f, 1.0f + __expf(-a));
}

__global__ void __launch_bounds__(THREADS)
voxel_raster_kernel(const float* __restrict__ positions,   // [N,3]
                    const float* __restrict__ sizes,       // [N]
                    const float* __restrict__ densities,   // [N]
                    const float* __restrict__ colors,      // [N, 27]
                    const float* __restrict__ ray_o,       // [B,3]
                    const float* __restrict__ ray_d,       // [B,3]
                    float* __restrict__ out)               // rgb[3B] | depth[B] | weight[B]
{
    __shared__ unsigned long long s_keys[CAP];
    __shared__ float s_tf_src[CAP];
    __shared__ float s_tf_dst[CAP];
    __shared__ int   s_cnt;

    const int b    = blockIdx.x;
    const int warp = threadIdx.x >> 5;
    const int lane = threadIdx.x & 31;

    if (threadIdx.x == 0) s_cnt = 0;
    __syncthreads();

    const float ox = ray_o[b * 3 + 0];
    const float oy = ray_o[b * 3 + 1];
    const float oz = ray_o[b * 3 + 2];
    const float dx = ray_d[b * 3 + 0];
    const float dy = ray_d[b * 3 + 1];
    const float dz = ray_d[b * 3 + 2];
    // exact divides: these feed the hit predicate (only 3 per thread, not hot)
    const float ix = 1.0f / dx, iy = 1.0f / dy, iz = 1.0f / dz;
    const float nx = -ox * ix, ny = -oy * iy, nz = -oz * iz;
    const float axr = fabsf(ix), ayr = fabsf(iy), azr = fabsf(iz);

    const float2* __restrict__ pos2 = (const float2*)positions;
    const float2* __restrict__ sz2  = (const float2*)sizes;

    // ---------------- Phase 1: paired slab tests (float2 loads) ----------------
    #pragma unroll
    for (int i = 0; i < PAIRS_PER_WARP / 32; i++) {
        const int p = warp * PAIRS_PER_WARP + i * 32 + lane;   // voxel pair index
        // pair (2p, 2p+1): floats [6p, 6p+6) -> 3 aligned float2
        const float2 ab = pos2[3 * p + 0];   // x0, y0
        const float2 cd = pos2[3 * p + 1];   // z0, x1
        const float2 ef = pos2[3 * p + 2];   // y1, z1
        const float2 hh = sz2[p];            // s0, s1

        // voxel 2p
        {
            const float h = 0.5f * hh.x;
            const float tcx = fmaf(ab.x, ix, nx);
            const float tcy = fmaf(ab.y, iy, ny);
            const float tcz = fmaf(cd.x, iz, nz);
            const float ex = h * axr, ey = h * ayr, ez = h * azr;
            const float tn = fmaxf(fmaxf(tcx - ex, tcy - ey), tcz - ez);
            const float tf = fminf(fminf(tcx + ex, tcy + ey), tcz + ez);
            if (tf > fmaxf(tn, 0.0f)) {
                const int slot = atomicAdd(&s_cnt, 1);
                if (slot < CAP) {
                    s_keys[slot]   = ((unsigned long long)f2u(tn) << 32) | (unsigned)(2 * p);
                    s_tf_src[slot] = tf;
                }
            }
        }
        // voxel 2p+1
        {
            const float h = 0.5f * hh.y;
            const float tcx = fmaf(cd.y, ix, nx);
            const float tcy = fmaf(ef.x, iy, ny);
            const float tcz = fmaf(ef.y, iz, nz);
            const float ex = h * axr, ey = h * ayr, ez = h * azr;
            const float tn = fmaxf(fmaxf(tcx - ex, tcy - ey), tcz - ez);
            const float tf = fminf(fminf(tcx + ex, tcy + ey), tcz + ez);
            if (tf > fmaxf(tn, 0.0f)) {
                const int slot = atomicAdd(&s_cnt, 1);
                if (slot < CAP) {
                    s_keys[slot]   = ((unsigned long long)f2u(tn) << 32) | (unsigned)(2 * p + 1);
                    s_tf_src[slot] = tf;
                }
            }
        }
    }
    __syncthreads();

    // ---------------- Phases 2+3: warp 0 only ----------------
    if (warp != 0) return;

    const int n = min(s_cnt, CAP);

    // ---- rank sort by (tn, voxel idx); keys are unique 64-bit ----
    {
        unsigned long long myk[CHUNKS];
        float mytf[CHUNKS];
        int   myr[CHUNKS];
        #pragma unroll
        for (int c = 0; c < CHUNKS; c++) {
            const int e = c * 32 + lane;
            myr[c] = -1;
            if (e < n) {
                const unsigned long long k = s_keys[e];
                int r = 0;
                for (int j = 0; j < n; j++) r += (s_keys[j] < k);
                myk[c]  = k;
                mytf[c] = s_tf_src[e];
                myr[c]  = r;
            }
        }
        __syncwarp();
        #pragma unroll
        for (int c = 0; c < CHUNKS; c++)
            if (myr[c] >= 0) { s_keys[myr[c]] = myk[c]; s_tf_dst[myr[c]] = mytf[c]; }
        __syncwarp();
    }

    // SH degree-2 basis, reference order: [1, y, z, x, xy, yz, 3z^2-1, xz, x^2-y^2]
    float sh[N_SH];
    sh[0] = 1.0f;
    sh[1] = dy;  sh[2] = dz;  sh[3] = dx;
    sh[4] = dx * dy;  sh[5] = dy * dz;
    sh[6] = 3.0f * dz * dz - 1.0f;
    sh[7] = dx * dz;  sh[8] = dx * dx - dy * dy;

    // ---- warp-parallel composite: prefix-product scan per 32-chunk ----
    float T_carry = 1.0f;
    float rA = 0.0f, gA = 0.0f, bA = 0.0f, dA = 0.0f, wA = 0.0f;

    for (int base = 0; base < n; base += 32) {
        const int e = base + lane;
        float ws = 0.0f, dp = 0.0f, cr = 0.0f, cg = 0.0f, cb = 0.0f;

        if (e < n) {
            const unsigned long long key = s_keys[e];
            const unsigned v  = (unsigned)(key & 0xFFFFFFFFu);
            unsigned tu = (unsigned)(key >> 32);
            const float tn = __uint_as_float((tu & 0x80000000u) ? (tu & 0x7FFFFFFFu) : ~tu);
            const float tf = s_tf_dst[e];

            const float sigma = __expf(densities[v]);
            const float span  = tf - tn;
            const float delta = span * (1.0f / (float)NS);
            const float alpha = 1.0f - __expf(-sigma * delta);
            const float bse   = 1.0f - alpha + 1e-8f;

            float pw = 1.0f;
            #pragma unroll
            for (int s = 0; s < NS; s++) {
                const float w  = alpha * pw;
                const float ts = tn + span * ((float)s / (float)(NS - 1));
                ws += w;
                dp += w * ts;
                pw *= bse;
            }

            const float* c = colors + v * (3 * N_SH);
            float a0 = 0.0f, a1 = 0.0f, a2 = 0.0f;
            #pragma unroll
            for (int k = 0; k < N_SH; k++) {
                a0 += sh[k] * c[k];
                a1 += sh[k] * c[N_SH + k];
                a2 += sh[k] * c[2 * N_SH + k];
            }
            cr = fast_sigmoid(a0);
            cg = fast_sigmoid(a1);
            cb = fast_sigmoid(a2);
        }

        // inclusive prefix product of one_m (inactive lanes contribute 1.0)
        float pp = 1.0f - ws;
        #pragma unroll
        for (int off = 1; off < 32; off <<= 1) {
            const float vv = __shfl_up_sync(FULL, pp, off);
            if (lane >= off) pp *= vv;
        }
        float ex = __shfl_up_sync(FULL, pp, 1);
        if (lane == 0) ex = 1.0f;
        const float Tb = T_carry * ex;

        const float procf   = (Tb >= EARLY_STOP_T) ? 1.0f : 0.0f;
        const float contrib = Tb * ws * procf;
        rA += contrib * cr;
        gA += contrib * cg;
        bA += contrib * cb;
        dA += Tb * procf * dp;
        wA += contrib;

        T_carry *= __shfl_sync(FULL, pp, 31);
        if (T_carry < EARLY_STOP_T && base + 32 < n) break;  // all later proc = 0
    }

    // warp reductions
    #pragma unroll
    for (int off = 16; off > 0; off >>= 1) {
        rA += __shfl_down_sync(FULL, rA, off);
        gA += __shfl_down_sync(FULL, gA, off);
        bA += __shfl_down_sync(FULL, bA, off);
        dA += __shfl_down_sync(FULL, dA, off);
        wA += __shfl_down_sync(FULL, wA, off);
    }

    if (lane == 0) {
        out[b * 3 + 0] = rA;
        out[b * 3 + 1] = gA;
        out[b * 3 + 2] = bA;
        out[NUM_RAYS * 3 + b] = (n > 0) ? dA : FAR_PLANE;   // has_hit == (n > 0)
        out[NUM_RAYS * 4 + b] = wA;
    }
}

extern "C" void kernel_launch(void* const* d_in, const int* in_sizes, int n_in,
                              void* d_out, int out_size) {
    const float* positions = (const float*)d_in[0];
    const float* sizes     = (const float*)d_in[1];
    const float* densities = (const float*)d_in[2];
    const float* colors    = (const float*)d_in[3];
    const float* ray_o     = (const float*)d_in[4];
    const float* ray_d     = (const float*)d_in[5];
    float* out = (float*)d_out;

    voxel_raster_kernel<<<NUM_RAYS, THREADS>>>(positions, sizes, densities, colors,
                                               ray_o, ray_d, out);
}

// round 8
// speedup vs baseline: 1.0058x; 1.0029x over previous
#include <cuda_runtime.h>

#define N_VOX        1024
#define NUM_RAYS     2048
#define N_SH         9
#define NS           8
#define THREADS      128           // 4 warps cooperating on ONE ray
#define WARPS        4
#define VOX_PER_WARP (N_VOX / WARPS)   // 256 -> 8 tests per lane
#define CAP          256
#define CHUNKS       (CAP / 32)
#define EARLY_STOP_T 0.01f
#define FAR_PLANE    100.0f
#define FULL         0xffffffffu

// float -> order-preserving uint32 (ascending float == ascending uint)
__device__ __forceinline__ unsigned f2u(float f) {
    unsigned u = __float_as_uint(f);
    return (u & 0x80000000u) ? ~u : (u | 0x80000000u);
}

__device__ __forceinline__ float fast_sigmoid(float a) {
    return __fdividef(1.0f, 1.0f + __expf(-a));
}

__global__ void __launch_bounds__(THREADS)
voxel_raster_kernel(const float* __restrict__ positions,   // [N,3]
                    const float* __restrict__ sizes,       // [N]
                    const float* __restrict__ densities,   // [N]
                    const float* __restrict__ colors,      // [N, 27]
                    const float* __restrict__ ray_o,       // [B,3]
                    const float* __restrict__ ray_d,       // [B,3]
                    float* __restrict__ out)               // rgb[3B] | depth[B] | weight[B]
{
    __shared__ unsigned long long s_keys[CAP];
    __shared__ float s_tf_src[CAP];
    __shared__ float s_tf_dst[CAP];
    __shared__ int   s_cnt;

    const int b    = blockIdx.x;
    const int warp = threadIdx.x >> 5;
    const int lane = threadIdx.x & 31;

    if (threadIdx.x == 0) s_cnt = 0;
    __syncthreads();

    const float ox = ray_o[b * 3 + 0];
    const float oy = ray_o[b * 3 + 1];
    const float oz = ray_o[b * 3 + 2];
    const float dx = ray_d[b * 3 + 0];
    const float dy = ray_d[b * 3 + 1];
    const float dz = ray_d[b * 3 + 2];
    // exact divides: these feed the hit predicate
    const float ix = 1.0f / dx, iy = 1.0f / dy, iz = 1.0f / dz;
    const float nx = -ox * ix, ny = -oy * iy, nz = -oz * iz;
    const float axr = fabsf(ix), ayr = fabsf(iy), azr = fabsf(iz);

    // ---------------- Phase 1: slab tests, predicated push ----------------
    #pragma unroll
    for (int i = 0; i < VOX_PER_WARP / 32; i++) {
        const int v = warp * VOX_PER_WARP + i * 32 + lane;

        const float px = positions[v * 3 + 0];
        const float py = positions[v * 3 + 1];
        const float pz = positions[v * 3 + 2];
        const float h  = 0.5f * sizes[v];

        const float tcx = fmaf(px, ix, nx);
        const float tcy = fmaf(py, iy, ny);
        const float tcz = fmaf(pz, iz, nz);
        const float hx = h * axr, hy = h * ayr, hz = h * azr;

        const float tn = fmaxf(fmaxf(tcx - hx, tcy - hy), tcz - hz);
        const float tf = fminf(fminf(tcx + hx, tcy + hy), tcz + hz);

        if (tf > fmaxf(tn, 0.0f)) {
            // clamped slot write keeps this region branch-predicable (no BSSY arm)
            const int slot = min(atomicAdd(&s_cnt, 1), CAP - 1);
            s_keys[slot]   = ((unsigned long long)f2u(tn) << 32) | (unsigned)v;
            s_tf_src[slot] = tf;
        }
    }
    __syncthreads();

    // ---------------- Phases 2+3: warp 0 only ----------------
    if (warp != 0) return;

    const int n = min(s_cnt, CAP);

    // ---- rank sort by (tn, voxel idx); keys are unique 64-bit ----
    if (n > 1) {
        unsigned long long myk[CHUNKS];
        float mytf[CHUNKS];
        int   myr[CHUNKS];
        #pragma unroll
        for (int c = 0; c < CHUNKS; c++) {
            const int e = c * 32 + lane;
            myr[c] = -1;
            if (e < n) {
                const unsigned long long k = s_keys[e];
                int r = 0;
                for (int j = 0; j < n; j++) r += (s_keys[j] < k);
                myk[c]  = k;
                mytf[c] = s_tf_src[e];
                myr[c]  = r;
            }
        }
        __syncwarp();
        #pragma unroll
        for (int c = 0; c < CHUNKS; c++)
            if (myr[c] >= 0) { s_keys[myr[c]] = myk[c]; s_tf_dst[myr[c]] = mytf[c]; }
        __syncwarp();
    } else if (n == 1) {
        if (lane == 0) s_tf_dst[0] = s_tf_src[0];
        __syncwarp();
    }

    // SH degree-2 basis, reference order: [1, y, z, x, xy, yz, 3z^2-1, xz, x^2-y^2]
    float sh[N_SH];
    sh[0] = 1.0f;
    sh[1] = dy;  sh[2] = dz;  sh[3] = dx;
    sh[4] = dx * dy;  sh[5] = dy * dz;
    sh[6] = 3.0f * dz * dz - 1.0f;
    sh[7] = dx * dz;  sh[8] = dx * dx - dy * dy;

    // ---- warp-parallel composite: prefix-product scan per 32-chunk ----
    float T_carry = 1.0f;
    float rA = 0.0f, gA = 0.0f, bA = 0.0f, dA = 0.0f, wA = 0.0f;

    for (int base = 0; base < n; base += 32) {
        const int e = base + lane;
        float ws = 0.0f, dp = 0.0f, cr = 0.0f, cg = 0.0f, cb = 0.0f;

        if (e < n) {
            const unsigned long long key = s_keys[e];
            const unsigned v  = (unsigned)(key & 0xFFFFFFFFu);
            unsigned tu = (unsigned)(key >> 32);
            const float tn = __uint_as_float((tu & 0x80000000u) ? (tu & 0x7FFFFFFFu) : ~tu);
            const float tf = s_tf_dst[e];

            const float sigma = __expf(densities[v]);
            const float span  = tf - tn;
            const float delta = span * (1.0f / (float)NS);
            const float alpha = 1.0f - __expf(-sigma * delta);
            const float bse   = 1.0f - alpha + 1e-8f;

            float pw = 1.0f;
            #pragma unroll
            for (int s = 0; s < NS; s++) {
                const float w  = alpha * pw;
                const float ts = tn + span * ((float)s / (float)(NS - 1));
                ws += w;
                dp += w * ts;
                pw *= bse;
            }

            const float* c = colors + v * (3 * N_SH);
            float a0 = 0.0f, a1 = 0.0f, a2 = 0.0f;
            #pragma unroll
            for (int k = 0; k < N_SH; k++) {
                a0 += sh[k] * c[k];
                a1 += sh[k] * c[N_SH + k];
                a2 += sh[k] * c[2 * N_SH + k];
            }
            cr = fast_sigmoid(a0);
            cg = fast_sigmoid(a1);
            cb = fast_sigmoid(a2);
        }

        // inclusive prefix product of one_m (inactive lanes contribute 1.0)
        float pp = 1.0f - ws;
        #pragma unroll
        for (int off = 1; off < 32; off <<= 1) {
            const float vv = __shfl_up_sync(FULL, pp, off);
            if (lane >= off) pp *= vv;
        }
        float ex = __shfl_up_sync(FULL, pp, 1);
        if (lane == 0) ex = 1.0f;
        const float Tb = T_carry * ex;

        const float procf   = (Tb >= EARLY_STOP_T) ? 1.0f : 0.0f;
        const float contrib = Tb * ws * procf;
        rA += contrib * cr;
        gA += contrib * cg;
        bA += contrib * cb;
        dA += Tb * procf * dp;
        wA += contrib;

        T_carry *= __shfl_sync(FULL, pp, 31);
        if (T_carry < EARLY_STOP_T && base + 32 < n) break;  // all later proc = 0
    }

    // warp reductions
    #pragma unroll
    for (int off = 16; off > 0; off >>= 1) {
        rA += __shfl_down_sync(FULL, rA, off);
        gA += __shfl_down_sync(FULL, gA, off);
        bA += __shfl_down_sync(FULL, bA, off);
        dA += __shfl_down_sync(FULL, dA, off);
        wA += __shfl_down_sync(FULL, wA, off);
    }

    if (lane == 0) {
        out[b * 3 + 0] = rA;
        out[b * 3 + 1] = gA;
        out[b * 3 + 2] = bA;
        out[NUM_RAYS * 3 + b] = (n > 0) ? dA : FAR_PLANE;   // has_hit == (n > 0)
        out[NUM_RAYS * 4 + b] = wA;
    }
}

extern "C" void kernel_launch(void* const* d_in, const int* in_sizes, int n_in,
                              void* d_out, int out_size) {
    const float* positions = (const float*)d_in[0];
    const float* sizes     = (const float*)d_in[1];
    const float* densities = (const float*)d_in[2];
    const float* colors    = (const float*)d_in[3];
    const float* ray_o     = (const float*)d_in[4];
    const float* ray_d     = (const float*)d_in[5];
    float* out = (float*)d_out;

    voxel_raster_kernel<<<NUM_RAYS, THREADS>>>(positions, sizes, densities, colors,
                                               ray_o, ray_d, out);
}

// round 9
// speedup vs baseline: 1.0118x; 1.0059x over previous
#include <cuda_runtime.h>

#define N_VOX        1024
#define NUM_RAYS     2048
#define N_SH         9
#define NS           8
#define RAYS_PER_CTA 8
#define THREADS      256
#define VPT          (N_VOX / THREADS)     // 4 voxels resident per thread
#define CAP          128
#define CHUNKS       (CAP / 32)
#define EARLY_STOP_T 0.01f
#define FAR_PLANE    100.0f
#define FULL         0xffffffffu

// float -> order-preserving uint32 (ascending float == ascending uint)
__device__ __forceinline__ unsigned f2u(float f) {
    unsigned u = __float_as_uint(f);
    return (u & 0x80000000u) ? ~u : (u | 0x80000000u);
}

__device__ __forceinline__ float fast_sigmoid(float a) {
    return __fdividef(1.0f, 1.0f + __expf(-a));
}

__global__ void __launch_bounds__(THREADS)
voxel_raster_kernel(const float* __restrict__ positions,   // [N,3]
                    const float* __restrict__ sizes,       // [N]
                    const float* __restrict__ densities,   // [N]
                    const float* __restrict__ colors,      // [N, 27]
                    const float* __restrict__ ray_o,       // [B,3]
                    const float* __restrict__ ray_d,       // [B,3]
                    float* __restrict__ out)               // rgb[3B] | depth[B] | weight[B]
{
    __shared__ float s_ray[RAYS_PER_CTA][8];               // ix,iy,iz,nx,ny,nz,(pad)
    __shared__ int   s_cnt[RAYS_PER_CTA];
    __shared__ unsigned long long s_keys[RAYS_PER_CTA][CAP];
    __shared__ float s_tf_src[RAYS_PER_CTA][CAP];
    __shared__ float s_tf_dst[RAYS_PER_CTA][CAP];

    const int tid  = threadIdx.x;
    const int warp = tid >> 5;
    const int lane = tid & 31;

    // ---- ray setup: thread r computes ray r's params (exact divides) ----
    if (tid < RAYS_PER_CTA) {
        const int rb = blockIdx.x * RAYS_PER_CTA + tid;
        const float ox = ray_o[rb * 3 + 0];
        const float oy = ray_o[rb * 3 + 1];
        const float oz = ray_o[rb * 3 + 2];
        const float ix = 1.0f / ray_d[rb * 3 + 0];
        const float iy = 1.0f / ray_d[rb * 3 + 1];
        const float iz = 1.0f / ray_d[rb * 3 + 2];
        s_ray[tid][0] = ix;
        s_ray[tid][1] = iy;
        s_ray[tid][2] = iz;
        s_ray[tid][3] = -ox * ix;
        s_ray[tid][4] = -oy * iy;
        s_ray[tid][5] = -oz * iz;
        s_cnt[tid] = 0;
    }

    // ---- load this thread's 4 resident voxels (once per CTA, serves 8 rays) ----
    float vx[VPT], vy[VPT], vz[VPT], vh[VPT];
    #pragma unroll
    for (int k = 0; k < VPT; k++) {
        const int v = k * THREADS + tid;
        vx[k] = positions[v * 3 + 0];
        vy[k] = positions[v * 3 + 1];
        vz[k] = positions[v * 3 + 2];
        vh[k] = 0.5f * sizes[v];
    }
    __syncthreads();

    // ---------------- Phase 1: 8 rays x 4 resident voxels per thread ----------------
    #pragma unroll
    for (int r = 0; r < RAYS_PER_CTA; r++) {
        const float ix = s_ray[r][0], iy = s_ray[r][1], iz = s_ray[r][2];
        const float nx = s_ray[r][3], ny = s_ray[r][4], nz = s_ray[r][5];
        const float axr = fabsf(ix), ayr = fabsf(iy), azr = fabsf(iz);

        #pragma unroll
        for (int k = 0; k < VPT; k++) {
            const float tcx = fmaf(vx[k], ix, nx);
            const float tcy = fmaf(vy[k], iy, ny);
            const float tcz = fmaf(vz[k], iz, nz);
            const float hx = vh[k] * axr, hy = vh[k] * ayr, hz = vh[k] * azr;

            const float tn = fmaxf(fmaxf(tcx - hx, tcy - hy), tcz - hz);
            const float tf = fminf(fminf(tcx + hx, tcy + hy), tcz + hz);

            if (tf > fmaxf(tn, 0.0f)) {
                const int slot = atomicAdd(&s_cnt[r], 1);
                if (slot < CAP) {
                    const int v = k * THREADS + tid;
                    s_keys[r][slot]   = ((unsigned long long)f2u(tn) << 32) | (unsigned)v;
                    s_tf_src[r][slot] = tf;
                }
            }
        }
    }
    __syncthreads();

    // ---------------- Phases 2+3: warp w composites ray w ----------------
    const int b = blockIdx.x * RAYS_PER_CTA + warp;
    const int n = min(s_cnt[warp], CAP);

    // ---- rank sort by (tn, voxel idx); keys are unique 64-bit ----
    if (n > 1) {
        unsigned long long myk[CHUNKS];
        float mytf[CHUNKS];
        int   myr[CHUNKS];
        #pragma unroll
        for (int c = 0; c < CHUNKS; c++) {
            const int e = c * 32 + lane;
            myr[c] = -1;
            if (e < n) {
                const unsigned long long k = s_keys[warp][e];
                int rr = 0;
                for (int j = 0; j < n; j++) rr += (s_keys[warp][j] < k);
                myk[c]  = k;
                mytf[c] = s_tf_src[warp][e];
                myr[c]  = rr;
            }
        }
        __syncwarp();
        #pragma unroll
        for (int c = 0; c < CHUNKS; c++)
            if (myr[c] >= 0) { s_keys[warp][myr[c]] = myk[c]; s_tf_dst[warp][myr[c]] = mytf[c]; }
        __syncwarp();
    } else if (n == 1) {
        if (lane == 0) s_tf_dst[warp][0] = s_tf_src[warp][0];
        __syncwarp();
    }

    // SH degree-2 basis, reference order: [1, y, z, x, xy, yz, 3z^2-1, xz, x^2-y^2]
    const float dx = ray_d[b * 3 + 0];
    const float dy = ray_d[b * 3 + 1];
    const float dz = ray_d[b * 3 + 2];
    float sh[N_SH];
    sh[0] = 1.0f;
    sh[1] = dy;  sh[2] = dz;  sh[3] = dx;
    sh[4] = dx * dy;  sh[5] = dy * dz;
    sh[6] = 3.0f * dz * dz - 1.0f;
    sh[7] = dx * dz;  sh[8] = dx * dx - dy * dy;

    // ---- warp-parallel composite: prefix-product scan per 32-chunk ----
    float T_carry = 1.0f;
    float rA = 0.0f, gA = 0.0f, bA = 0.0f, dA = 0.0f, wA = 0.0f;

    for (int base = 0; base < n; base += 32) {
        const int e = base + lane;
        float ws = 0.0f, dp = 0.0f, cr = 0.0f, cg = 0.0f, cb = 0.0f;

        if (e < n) {
            const unsigned long long key = s_keys[warp][e];
            const unsigned v  = (unsigned)(key & 0xFFFFFFFFu);
            unsigned tu = (unsigned)(key >> 32);
            const float tn = __uint_as_float((tu & 0x80000000u) ? (tu & 0x7FFFFFFFu) : ~tu);
            const float tf = s_tf_dst[warp][e];

            const float sigma = __expf(densities[v]);
            const float span  = tf - tn;
            const float delta = span * (1.0f / (float)NS);
            const float alpha = 1.0f - __expf(-sigma * delta);
            const float bse   = 1.0f - alpha + 1e-8f;

            float pw = 1.0f;
            #pragma unroll
            for (int s = 0; s < NS; s++) {
                const float w  = alpha * pw;
                const float ts = tn + span * ((float)s / (float)(NS - 1));
                ws += w;
                dp += w * ts;
                pw *= bse;
            }

            const float* c = colors + v * (3 * N_SH);
            float a0 = 0.0f, a1 = 0.0f, a2 = 0.0f;
            #pragma unroll
            for (int k = 0; k < N_SH; k++) {
                a0 += sh[k] * c[k];
                a1 += sh[k] * c[N_SH + k];
                a2 += sh[k] * c[2 * N_SH + k];
            }
            cr = fast_sigmoid(a0);
            cg = fast_sigmoid(a1);
            cb = fast_sigmoid(a2);
        }

        // inclusive prefix product of one_m (inactive lanes contribute 1.0)
        float pp = 1.0f - ws;
        #pragma unroll
        for (int off = 1; off < 32; off <<= 1) {
            const float vv = __shfl_up_sync(FULL, pp, off);
            if (lane >= off) pp *= vv;
        }
        float exs = __shfl_up_sync(FULL, pp, 1);
        if (lane == 0) exs = 1.0f;
        const float Tb = T_carry * exs;

        const float procf   = (Tb >= EARLY_STOP_T) ? 1.0f : 0.0f;
        const float contrib = Tb * ws * procf;
        rA += contrib * cr;
        gA += contrib * cg;
        bA += contrib * cb;
        dA += Tb * procf * dp;
        wA += contrib;

        T_carry *= __shfl_sync(FULL, pp, 31);
        if (T_carry < EARLY_STOP_T && base + 32 < n) break;  // all later proc = 0
    }

    // warp reductions
    #pragma unroll
    for (int off = 16; off > 0; off >>= 1) {
        rA += __shfl_down_sync(FULL, rA, off);
        gA += __shfl_down_sync(FULL, gA, off);
        bA += __shfl_down_sync(FULL, bA, off);
        dA += __shfl_down_sync(FULL, dA, off);
        wA += __shfl_down_sync(FULL, wA, off);
    }

    if (lane == 0) {
        out[b * 3 + 0] = rA;
        out[b * 3 + 1] = gA;
        out[b * 3 + 2] = bA;
        out[NUM_RAYS * 3 + b] = (n > 0) ? dA : FAR_PLANE;   // has_hit == (n > 0)
        out[NUM_RAYS * 4 + b] = wA;
    }
}

extern "C" void kernel_launch(void* const* d_in, const int* in_sizes, int n_in,
                              void* d_out, int out_size) {
    const float* positions = (const float*)d_in[0];
    const float* sizes     = (const float*)d_in[1];
    const float* densities = (const float*)d_in[2];
    const float* colors    = (const float*)d_in[3];
    const float* ray_o     = (const float*)d_in[4];
    const float* ray_d     = (const float*)d_in[5];
    float* out = (float*)d_out;

    voxel_raster_kernel<<<NUM_RAYS / RAYS_PER_CTA, THREADS>>>(
        positions, sizes, densities, colors, ray_o, ray_d, out);
}